// round 14
// baseline (speedup 1.0000x reference)
#include <cuda_runtime.h>
#include <cstdint>
#include <cstddef>

// ============================================================================
// RNNLayers: 2-layer LSTM (Keras, activation=selu), B=64, T=2048, F=64, H=128.
//   1) GEMM1: xz = x  @ W1 + b1   -> g_xz   [131072 x 512]
//   2) scan1: LSTM recurrence     -> g_h1   (2 batch rows per CTA, 32 CTAs)
//   3) GEMM2: xz = h1 @ W2 + b2   -> g_xz
//   4) scan2: LSTM recurrence     -> d_out
//
// Scan design (single CTA per 2 rows — NO cluster, R12's per-step DSMEM sync
// regressed):
//   512 threads: gate = tid&3 (i,f,g,o), j = tid>>2 (h column). Thread owns
//   gate column ucol = gate*128+j for BOTH batch rows -> U registers/smem
//   loads amortize over 2 rows, and the two independent recurrence streams
//   give ILP-2 to hide LDS/MUFU/shuffle latency.
//   U column: k in [0,KREG) register-resident as f32x2 pairs; k in [KREG,128)
//   in smem [chunk][tid][4] (conflict-free LDS.128).  h double-buffered in
//   smem per row; gates gathered with 3 warp shuffles; ONE barrier per step.
// ============================================================================

typedef unsigned long long ull;

#define BATCH 64
#define TSEQ  2048
#define FIN   64
#define HID   128

#define SELU_LAM 1.0507009873554804934193349852946f
#define SELU_ALF 1.6732632423543772848170429916717f

__device__ float g_xz[(size_t)BATCH * TSEQ * 4 * HID];  // 256 MB scratch
__device__ float g_h1[(size_t)BATCH * TSEQ * HID];      //  64 MB scratch

__device__ __forceinline__ void fma2(ull& d, ull a, ull b) {
    asm("fma.rn.f32x2 %0, %1, %2, %0;" : "+l"(d) : "l"(a), "l"(b));
}
__device__ __forceinline__ ull pack2(float lo, float hi) {
    ull r; asm("mov.b64 %0, {%1, %2};" : "=l"(r) : "f"(lo), "f"(hi)); return r;
}
__device__ __forceinline__ float2 unpack2(ull v) {
    float2 r; asm("mov.b64 {%0, %1}, %2;" : "=f"(r.x), "=f"(r.y) : "l"(v)); return r;
}
__device__ __forceinline__ ull d2u(double d) { return (ull)__double_as_longlong(d); }

// ============================================================================
// GEMM: Y[M,512] = X[M,K] @ W[K,512] + bias.  BM=128, BN=128, K loaded whole.
// ============================================================================
template<int K>
__global__ __launch_bounds__(256, 1)
void gemm_xz(const float* __restrict__ X, const float* __restrict__ W,
             const float* __restrict__ bias, float* __restrict__ Y) {
    extern __shared__ float sm[];
    float* s_a = sm;                     // [128][K+1]
    float* s_b = sm + 128 * (K + 1);     // [K][128]
    const int tid = threadIdx.x;
    const int bm  = blockIdx.x * 128;
    const int bn  = blockIdx.y * 128;

    #pragma unroll 8
    for (int i = tid; i < 128 * K; i += 256) {
        int m = i / K, k = i - m * K;
        s_a[m * (K + 1) + k] = X[(size_t)(bm + m) * K + k];
    }
    #pragma unroll 4
    for (int i = tid * 4; i < K * 128; i += 1024) {
        int k = i >> 7, n = i & 127;
        *(float4*)(s_b + k * 128 + n) = *(const float4*)(W + (size_t)k * 512 + bn + n);
    }
    __syncthreads();

    const int tmi = tid & 15;
    const int tn  = (tid >> 4) << 3;
    ull acc[8][4] = {};
    const float* sbp = s_b + tn;

    #pragma unroll 4
    for (int k = 0; k < K; ++k) {
        float4 b0 = *(const float4*)(sbp + k * 128);
        float4 b1 = *(const float4*)(sbp + k * 128 + 4);
        ull bb0 = pack2(b0.x, b0.y), bb1 = pack2(b0.z, b0.w);
        ull bb2 = pack2(b1.x, b1.y), bb3 = pack2(b1.z, b1.w);
        #pragma unroll
        for (int r = 0; r < 8; ++r) {
            float a = s_a[(tmi + (r << 4)) * (K + 1) + k];
            ull aa = pack2(a, a);
            fma2(acc[r][0], aa, bb0);
            fma2(acc[r][1], aa, bb1);
            fma2(acc[r][2], aa, bb2);
            fma2(acc[r][3], aa, bb3);
        }
    }

    float4 bv0 = *(const float4*)(bias + bn + tn);
    float4 bv1 = *(const float4*)(bias + bn + tn + 4);
    #pragma unroll
    for (int r = 0; r < 8; ++r) {
        int row = bm + tmi + (r << 4);
        float2 c0 = unpack2(acc[r][0]);
        float2 c1 = unpack2(acc[r][1]);
        float2 c2 = unpack2(acc[r][2]);
        float2 c3 = unpack2(acc[r][3]);
        float4 o0 = make_float4(c0.x + bv0.x, c0.y + bv0.y, c1.x + bv0.z, c1.y + bv0.w);
        float4 o1 = make_float4(c2.x + bv1.x, c2.y + bv1.y, c3.x + bv1.z, c3.y + bv1.w);
        float* yp = Y + (size_t)row * 512 + bn + tn;
        *(float4*)yp       = o0;
        *(float4*)(yp + 4) = o1;
    }
}

// ============================================================================
// LSTM scan, 2 batch rows per CTA.
// ============================================================================
#define KREG 72
#define KSM  56

__global__ __launch_bounds__(512, 1)
void lstm_scan(const float* __restrict__ xz, const float* __restrict__ U,
               float* __restrict__ hout, int T) {
    extern __shared__ float sm[];
    float* s_u = sm;                       // [KSM/4][512][4]
    float* s_h = sm + (KSM / 4) * 2048;    // [2 rows][2 bufs][128]

    const int tid  = threadIdx.x;
    const int lane = tid & 31;
    const int gate = tid & 3;              // i, f, g, o
    const int j    = tid >> 2;             // 0..127
    const int ucol = (gate << 7) + j;
    const int b0   = blockIdx.x * 2;

    // ---- one-time U load ----------------------------------------------------
    ull ureg[KREG / 2];
    #pragma unroll
    for (int q = 0; q < KREG / 2; ++q) {
        float u0 = U[(size_t)(2 * q)     * 512 + ucol];
        float u1 = U[(size_t)(2 * q + 1) * 512 + ucol];
        ureg[q] = pack2(u0, u1);
    }
    #pragma unroll
    for (int kk = 0; kk < KSM; ++kk) {
        s_u[(kk >> 2) * 2048 + (tid << 2) + (kk & 3)] = U[(size_t)(KREG + kk) * 512 + ucol];
    }
    if (tid < HID) { s_h[tid] = 0.0f; s_h[256 + tid] = 0.0f; }  // buf0, both rows
    float c0 = 0.0f, c1 = 0.0f;
    __syncthreads();

    const float* xzp0 = xz + (size_t)b0 * T * 512 + ucol;
    const float* xzp1 = xzp0 + (size_t)T * 512;
    float* hp0 = hout + (size_t)b0 * T * HID + j;
    float* hp1 = hp0 + (size_t)T * HID;

    float xa0 = __ldcs(xzp0), xb0 = __ldcs(xzp0 + 512);
    float xa1 = __ldcs(xzp1), xb1 = __ldcs(xzp1 + 512);

    const int lb = lane & 28;              // 4-lane gate-group base

    for (int t = 0; t < T; ++t) {
        const int ib = t & 1;
        const int nb = ib ^ 1;
        const float* h0 = s_h + ib * 128;          // row0 current h
        const float* h1 = s_h + 256 + ib * 128;    // row1 current h

        // z_r = xz_r + dot(h_r, U[:,ucol]); 2 accumulator chains per row,
        // rows interleaved for ILP, U operands shared between rows.
        ull p0 = 0, q0 = 0, p1 = 0, q1 = 0;
        #pragma unroll
        for (int q = 0; q < KREG / 4; ++q) {
            double2 d0 = *(const double2*)(h0 + (q << 2));
            double2 d1 = *(const double2*)(h1 + (q << 2));
            fma2(p0, d2u(d0.x), ureg[2 * q]);
            fma2(p1, d2u(d1.x), ureg[2 * q]);
            fma2(q0, d2u(d0.y), ureg[2 * q + 1]);
            fma2(q1, d2u(d1.y), ureg[2 * q + 1]);
        }
        #pragma unroll
        for (int q = 0; q < KSM / 4; ++q) {
            double2 ud = *(const double2*)(s_u + q * 2048 + (tid << 2));
            double2 d0 = *(const double2*)(h0 + KREG + (q << 2));
            double2 d1 = *(const double2*)(h1 + KREG + (q << 2));
            fma2(p0, d2u(d0.x), d2u(ud.x));
            fma2(p1, d2u(d1.x), d2u(ud.x));
            fma2(q0, d2u(d0.y), d2u(ud.y));
            fma2(q1, d2u(d1.y), d2u(ud.y));
        }
        float2 e0 = unpack2(p0), f0 = unpack2(q0);
        float2 e1 = unpack2(p1), f1 = unpack2(q1);
        float z0 = xa0 + ((e0.x + e0.y) + (f0.x + f0.y));
        float z1 = xa1 + ((e1.x + e1.y) + (f1.x + f1.y));

        // rotate xz prefetch (depth 2)
        int tp = (t + 2 < T) ? t + 2 : t;
        xa0 = xb0; xb0 = __ldcs(xzp0 + (size_t)tp * 512);
        xa1 = xb1; xb1 = __ldcs(xzp1 + (size_t)tp * 512);

        // activations (sigmoid for i/f/o, selu for g), both rows
        float ex0  = __expf(gate == 2 ? z0 : -z0);
        float ex1  = __expf(gate == 2 ? z1 : -z1);
        float sg0  = __fdividef(1.0f, 1.0f + ex0);
        float sg1  = __fdividef(1.0f, 1.0f + ex1);
        float act0 = (gate == 2)
                   ? ((z0 > 0.0f) ? SELU_LAM * z0 : (SELU_LAM * SELU_ALF) * (ex0 - 1.0f))
                   : sg0;
        float act1 = (gate == 2)
                   ? ((z1 > 0.0f) ? SELU_LAM * z1 : (SELU_LAM * SELU_ALF) * (ex1 - 1.0f))
                   : sg1;

        // gather gates f, g, o into the gate==0 lane (3 shuffles per row)
        float af0 = __shfl_sync(0xffffffffu, act0, lb | 1);
        float af1 = __shfl_sync(0xffffffffu, act1, lb | 1);
        float ag0 = __shfl_sync(0xffffffffu, act0, lb | 2);
        float ag1 = __shfl_sync(0xffffffffu, act1, lb | 2);
        float ao0 = __shfl_sync(0xffffffffu, act0, lb | 3);
        float ao1 = __shfl_sync(0xffffffffu, act1, lb | 3);

        if (gate == 0) {
            c0 = af0 * c0 + act0 * ag0;
            c1 = af1 * c1 + act1 * ag1;
            float sc0 = (c0 > 0.0f) ? SELU_LAM * c0
                                    : (SELU_LAM * SELU_ALF) * (__expf(c0) - 1.0f);
            float sc1 = (c1 > 0.0f) ? SELU_LAM * c1
                                    : (SELU_LAM * SELU_ALF) * (__expf(c1) - 1.0f);
            float hh0 = ao0 * sc0;
            float hh1 = ao1 * sc1;
            s_h[nb * 128 + j]       = hh0;
            s_h[256 + nb * 128 + j] = hh1;
            hp0[(size_t)t * HID] = hh0;
            hp1[(size_t)t * HID] = hh1;
        }
        __syncthreads();
    }
}

// ============================================================================
// kernel_launch — inputs: x, W1, U1, b1, W2, U2, b2 (fp32); out: [B,T,H] fp32.
// ============================================================================
extern "C" void kernel_launch(void* const* d_in, const int* in_sizes, int n_in,
                              void* d_out, int out_size) {
    (void)in_sizes; (void)n_in; (void)out_size;
    const float* x  = (const float*)d_in[0];
    const float* W1 = (const float*)d_in[1];
    const float* U1 = (const float*)d_in[2];
    const float* b1 = (const float*)d_in[3];
    const float* W2 = (const float*)d_in[4];
    const float* U2 = (const float*)d_in[5];
    const float* b2 = (const float*)d_in[6];
    float* out = (float*)d_out;

    void *pxz = nullptr, *ph1 = nullptr;
    cudaGetSymbolAddress(&pxz, g_xz);
    cudaGetSymbolAddress(&ph1, g_h1);
    float* xz = (float*)pxz;
    float* h1 = (float*)ph1;

    const int smemA = (128 * (FIN + 1) + FIN * 128) * 4;    //  66048 B
    const int smemB = (128 * (HID + 1) + HID * 128) * 4;    // 131584 B
    const int smemS = ((KSM / 4) * 2048 + 512) * 4;         // 116736 B
    cudaFuncSetAttribute(gemm_xz<FIN>, cudaFuncAttributeMaxDynamicSharedMemorySize, smemA);
    cudaFuncSetAttribute(gemm_xz<HID>, cudaFuncAttributeMaxDynamicSharedMemorySize, smemB);
    cudaFuncSetAttribute(lstm_scan,    cudaFuncAttributeMaxDynamicSharedMemorySize, smemS);

    dim3 gg((BATCH * TSEQ) / 128, 4);

    gemm_xz<FIN><<<gg, 256, smemA>>>(x, W1, b1, xz);
    lstm_scan<<<BATCH / 2, 512, smemS>>>(xz, U1, h1, TSEQ);
    gemm_xz<HID><<<gg, 256, smemB>>>(h1, W2, b2, xz);
    lstm_scan<<<BATCH / 2, 512, smemS>>>(xz, U2, out, TSEQ);
}

// round 15
// speedup vs baseline: 1.0051x; 1.0051x over previous
#include <cuda_runtime.h>
#include <cstdint>
#include <cstddef>

// ============================================================================
// RNNLayers: 2-layer LSTM (Keras, activation=selu), B=64, T=2048, F=64, H=128.
//   1) GEMM1: xz = x  @ W1 + b1   -> g_xz   [131072 x 512]
//   2) scan1: LSTM recurrence     -> g_h1   (2 batch rows per CTA, 32 CTAs)
//   3) GEMM2: xz = h1 @ W2 + b2   -> g_xz
//   4) scan2: LSTM recurrence     -> d_out
//
// Scan design (single CTA per 2 rows — NO cluster, R12's per-step DSMEM sync
// regressed):
//   512 threads: gate = tid&3 (i,f,g,o), j = tid>>2 (h column). Thread owns
//   gate column ucol = gate*128+j for BOTH batch rows -> U registers/smem
//   loads amortize over 2 rows, and the two independent recurrence streams
//   give ILP-2 to hide LDS/MUFU/shuffle latency.
//   U column: k in [0,KREG) register-resident as f32x2 pairs; k in [KREG,128)
//   in smem [chunk][tid][4] (conflict-free LDS.128).  h double-buffered in
//   smem per row; gates gathered with 3 warp shuffles; ONE barrier per step.
// ============================================================================

typedef unsigned long long ull;

#define BATCH 64
#define TSEQ  2048
#define FIN   64
#define HID   128

#define SELU_LAM 1.0507009873554804934193349852946f
#define SELU_ALF 1.6732632423543772848170429916717f

__device__ float g_xz[(size_t)BATCH * TSEQ * 4 * HID];  // 256 MB scratch
__device__ float g_h1[(size_t)BATCH * TSEQ * HID];      //  64 MB scratch

__device__ __forceinline__ void fma2(ull& d, ull a, ull b) {
    asm("fma.rn.f32x2 %0, %1, %2, %0;" : "+l"(d) : "l"(a), "l"(b));
}
__device__ __forceinline__ ull pack2(float lo, float hi) {
    ull r; asm("mov.b64 %0, {%1, %2};" : "=l"(r) : "f"(lo), "f"(hi)); return r;
}
__device__ __forceinline__ float2 unpack2(ull v) {
    float2 r; asm("mov.b64 {%0, %1}, %2;" : "=f"(r.x), "=f"(r.y) : "l"(v)); return r;
}
__device__ __forceinline__ ull d2u(double d) { return (ull)__double_as_longlong(d); }

// ============================================================================
// GEMM: Y[M,512] = X[M,K] @ W[K,512] + bias.  BM=128, BN=128, K loaded whole.
// ============================================================================
template<int K>
__global__ __launch_bounds__(256, 1)
void gemm_xz(const float* __restrict__ X, const float* __restrict__ W,
             const float* __restrict__ bias, float* __restrict__ Y) {
    extern __shared__ float sm[];
    float* s_a = sm;                     // [128][K+1]
    float* s_b = sm + 128 * (K + 1);     // [K][128]
    const int tid = threadIdx.x;
    const int bm  = blockIdx.x * 128;
    const int bn  = blockIdx.y * 128;

    #pragma unroll 8
    for (int i = tid; i < 128 * K; i += 256) {
        int m = i / K, k = i - m * K;
        s_a[m * (K + 1) + k] = X[(size_t)(bm + m) * K + k];
    }
    #pragma unroll 4
    for (int i = tid * 4; i < K * 128; i += 1024) {
        int k = i >> 7, n = i & 127;
        *(float4*)(s_b + k * 128 + n) = *(const float4*)(W + (size_t)k * 512 + bn + n);
    }
    __syncthreads();

    const int tmi = tid & 15;
    const int tn  = (tid >> 4) << 3;
    ull acc[8][4] = {};
    const float* sbp = s_b + tn;

    #pragma unroll 4
    for (int k = 0; k < K; ++k) {
        float4 b0 = *(const float4*)(sbp + k * 128);
        float4 b1 = *(const float4*)(sbp + k * 128 + 4);
        ull bb0 = pack2(b0.x, b0.y), bb1 = pack2(b0.z, b0.w);
        ull bb2 = pack2(b1.x, b1.y), bb3 = pack2(b1.z, b1.w);
        #pragma unroll
        for (int r = 0; r < 8; ++r) {
            float a = s_a[(tmi + (r << 4)) * (K + 1) + k];
            ull aa = pack2(a, a);
            fma2(acc[r][0], aa, bb0);
            fma2(acc[r][1], aa, bb1);
            fma2(acc[r][2], aa, bb2);
            fma2(acc[r][3], aa, bb3);
        }
    }

    float4 bv0 = *(const float4*)(bias + bn + tn);
    float4 bv1 = *(const float4*)(bias + bn + tn + 4);
    #pragma unroll
    for (int r = 0; r < 8; ++r) {
        int row = bm + tmi + (r << 4);
        float2 c0 = unpack2(acc[r][0]);
        float2 c1 = unpack2(acc[r][1]);
        float2 c2 = unpack2(acc[r][2]);
        float2 c3 = unpack2(acc[r][3]);
        float4 o0 = make_float4(c0.x + bv0.x, c0.y + bv0.y, c1.x + bv0.z, c1.y + bv0.w);
        float4 o1 = make_float4(c2.x + bv1.x, c2.y + bv1.y, c3.x + bv1.z, c3.y + bv1.w);
        float* yp = Y + (size_t)row * 512 + bn + tn;
        *(float4*)yp       = o0;
        *(float4*)(yp + 4) = o1;
    }
}

// ============================================================================
// LSTM scan, 2 batch rows per CTA.
// ============================================================================
#define KREG 72
#define KSM  56

__global__ __launch_bounds__(512, 1)
void lstm_scan(const float* __restrict__ xz, const float* __restrict__ U,
               float* __restrict__ hout, int T) {
    extern __shared__ float sm[];
    float* s_u = sm;                       // [KSM/4][512][4]
    float* s_h = sm + (KSM / 4) * 2048;    // [2 rows][2 bufs][128]

    const int tid  = threadIdx.x;
    const int lane = tid & 31;
    const int gate = tid & 3;              // i, f, g, o
    const int j    = tid >> 2;             // 0..127
    const int ucol = (gate << 7) + j;
    const int b0   = blockIdx.x * 2;

    // ---- one-time U load ----------------------------------------------------
    ull ureg[KREG / 2];
    #pragma unroll
    for (int q = 0; q < KREG / 2; ++q) {
        float u0 = U[(size_t)(2 * q)     * 512 + ucol];
        float u1 = U[(size_t)(2 * q + 1) * 512 + ucol];
        ureg[q] = pack2(u0, u1);
    }
    #pragma unroll
    for (int kk = 0; kk < KSM; ++kk) {
        s_u[(kk >> 2) * 2048 + (tid << 2) + (kk & 3)] = U[(size_t)(KREG + kk) * 512 + ucol];
    }
    if (tid < HID) { s_h[tid] = 0.0f; s_h[256 + tid] = 0.0f; }  // buf0, both rows
    float c0 = 0.0f, c1 = 0.0f;
    __syncthreads();

    const float* xzp0 = xz + (size_t)b0 * T * 512 + ucol;
    const float* xzp1 = xzp0 + (size_t)T * 512;
    float* hp0 = hout + (size_t)b0 * T * HID + j;
    float* hp1 = hp0 + (size_t)T * HID;

    float xa0 = __ldcs(xzp0), xb0 = __ldcs(xzp0 + 512);
    float xa1 = __ldcs(xzp1), xb1 = __ldcs(xzp1 + 512);

    const int lb = lane & 28;              // 4-lane gate-group base

    for (int t = 0; t < T; ++t) {
        const int ib = t & 1;
        const int nb = ib ^ 1;
        const float* h0 = s_h + ib * 128;          // row0 current h
        const float* h1 = s_h + 256 + ib * 128;    // row1 current h

        // z_r = xz_r + dot(h_r, U[:,ucol]); 2 accumulator chains per row,
        // rows interleaved for ILP, U operands shared between rows.
        ull p0 = 0, q0 = 0, p1 = 0, q1 = 0;
        #pragma unroll
        for (int q = 0; q < KREG / 4; ++q) {
            double2 d0 = *(const double2*)(h0 + (q << 2));
            double2 d1 = *(const double2*)(h1 + (q << 2));
            fma2(p0, d2u(d0.x), ureg[2 * q]);
            fma2(p1, d2u(d1.x), ureg[2 * q]);
            fma2(q0, d2u(d0.y), ureg[2 * q + 1]);
            fma2(q1, d2u(d1.y), ureg[2 * q + 1]);
        }
        #pragma unroll
        for (int q = 0; q < KSM / 4; ++q) {
            double2 ud = *(const double2*)(s_u + q * 2048 + (tid << 2));
            double2 d0 = *(const double2*)(h0 + KREG + (q << 2));
            double2 d1 = *(const double2*)(h1 + KREG + (q << 2));
            fma2(p0, d2u(d0.x), d2u(ud.x));
            fma2(p1, d2u(d1.x), d2u(ud.x));
            fma2(q0, d2u(d0.y), d2u(ud.y));
            fma2(q1, d2u(d1.y), d2u(ud.y));
        }
        float2 e0 = unpack2(p0), f0 = unpack2(q0);
        float2 e1 = unpack2(p1), f1 = unpack2(q1);
        float z0 = xa0 + ((e0.x + e0.y) + (f0.x + f0.y));
        float z1 = xa1 + ((e1.x + e1.y) + (f1.x + f1.y));

        // rotate xz prefetch (depth 2)
        int tp = (t + 2 < T) ? t + 2 : t;
        xa0 = xb0; xb0 = __ldcs(xzp0 + (size_t)tp * 512);
        xa1 = xb1; xb1 = __ldcs(xzp1 + (size_t)tp * 512);

        // activations (sigmoid for i/f/o, selu for g), both rows
        float ex0  = __expf(gate == 2 ? z0 : -z0);
        float ex1  = __expf(gate == 2 ? z1 : -z1);
        float sg0  = __fdividef(1.0f, 1.0f + ex0);
        float sg1  = __fdividef(1.0f, 1.0f + ex1);
        float act0 = (gate == 2)
                   ? ((z0 > 0.0f) ? SELU_LAM * z0 : (SELU_LAM * SELU_ALF) * (ex0 - 1.0f))
                   : sg0;
        float act1 = (gate == 2)
                   ? ((z1 > 0.0f) ? SELU_LAM * z1 : (SELU_LAM * SELU_ALF) * (ex1 - 1.0f))
                   : sg1;

        // gather gates f, g, o into the gate==0 lane (3 shuffles per row)
        float af0 = __shfl_sync(0xffffffffu, act0, lb | 1);
        float af1 = __shfl_sync(0xffffffffu, act1, lb | 1);
        float ag0 = __shfl_sync(0xffffffffu, act0, lb | 2);
        float ag1 = __shfl_sync(0xffffffffu, act1, lb | 2);
        float ao0 = __shfl_sync(0xffffffffu, act0, lb | 3);
        float ao1 = __shfl_sync(0xffffffffu, act1, lb | 3);

        if (gate == 0) {
            c0 = af0 * c0 + act0 * ag0;
            c1 = af1 * c1 + act1 * ag1;
            float sc0 = (c0 > 0.0f) ? SELU_LAM * c0
                                    : (SELU_LAM * SELU_ALF) * (__expf(c0) - 1.0f);
            float sc1 = (c1 > 0.0f) ? SELU_LAM * c1
                                    : (SELU_LAM * SELU_ALF) * (__expf(c1) - 1.0f);
            float hh0 = ao0 * sc0;
            float hh1 = ao1 * sc1;
            s_h[nb * 128 + j]       = hh0;
            s_h[256 + nb * 128 + j] = hh1;
            hp0[(size_t)t * HID] = hh0;
            hp1[(size_t)t * HID] = hh1;
        }
        __syncthreads();
    }
}

// ============================================================================
// kernel_launch — inputs: x, W1, U1, b1, W2, U2, b2 (fp32); out: [B,T,H] fp32.
// ============================================================================
extern "C" void kernel_launch(void* const* d_in, const int* in_sizes, int n_in,
                              void* d_out, int out_size) {
    (void)in_sizes; (void)n_in; (void)out_size;
    const float* x  = (const float*)d_in[0];
    const float* W1 = (const float*)d_in[1];
    const float* U1 = (const float*)d_in[2];
    const float* b1 = (const float*)d_in[3];
    const float* W2 = (const float*)d_in[4];
    const float* U2 = (const float*)d_in[5];
    const float* b2 = (const float*)d_in[6];
    float* out = (float*)d_out;

    void *pxz = nullptr, *ph1 = nullptr;
    cudaGetSymbolAddress(&pxz, g_xz);
    cudaGetSymbolAddress(&ph1, g_h1);
    float* xz = (float*)pxz;
    float* h1 = (float*)ph1;

    const int smemA = (128 * (FIN + 1) + FIN * 128) * 4;    //  66048 B
    const int smemB = (128 * (HID + 1) + HID * 128) * 4;    // 131584 B
    const int smemS = ((KSM / 4) * 2048 + 512) * 4;         // 116736 B
    cudaFuncSetAttribute(gemm_xz<FIN>, cudaFuncAttributeMaxDynamicSharedMemorySize, smemA);
    cudaFuncSetAttribute(gemm_xz<HID>, cudaFuncAttributeMaxDynamicSharedMemorySize, smemB);
    cudaFuncSetAttribute(lstm_scan,    cudaFuncAttributeMaxDynamicSharedMemorySize, smemS);

    dim3 gg((BATCH * TSEQ) / 128, 4);

    gemm_xz<FIN><<<gg, 256, smemA>>>(x, W1, b1, xz);
    lstm_scan<<<BATCH / 2, 512, smemS>>>(xz, U1, h1, TSEQ);
    gemm_xz<HID><<<gg, 256, smemB>>>(h1, W2, b2, xz);
    lstm_scan<<<BATCH / 2, 512, smemS>>>(xz, U2, out, TSEQ);
}

// round 16
// speedup vs baseline: 1.0057x; 1.0006x over previous
#include <cuda_runtime.h>
#include <cstdint>
#include <cstddef>

// ============================================================================
// RNNLayers: 2-layer LSTM (Keras, activation=selu), B=64, T=2048, F=64, H=128.
//   1) GEMM1: xz = x  @ W1 + b1   -> g_xz   [131072 x 512]
//   2) scan1: LSTM recurrence     -> g_h1   (2 batch rows per CTA, 32 CTAs)
//   3) GEMM2: xz = h1 @ W2 + b2   -> g_xz
//   4) scan2: LSTM recurrence     -> d_out
//
// Scan design (single CTA per 2 rows — NO cluster, R12's per-step DSMEM sync
// regressed):
//   512 threads: gate = tid&3 (i,f,g,o), j = tid>>2 (h column). Thread owns
//   gate column ucol = gate*128+j for BOTH batch rows -> U registers/smem
//   loads amortize over 2 rows, and the two independent recurrence streams
//   give ILP-2 to hide LDS/MUFU/shuffle latency.
//   U column: k in [0,KREG) register-resident as f32x2 pairs; k in [KREG,128)
//   in smem [chunk][tid][4] (conflict-free LDS.128).  h double-buffered in
//   smem per row; gates gathered with 3 warp shuffles; ONE barrier per step.
// ============================================================================

typedef unsigned long long ull;

#define BATCH 64
#define TSEQ  2048
#define FIN   64
#define HID   128

#define SELU_LAM 1.0507009873554804934193349852946f
#define SELU_ALF 1.6732632423543772848170429916717f

__device__ float g_xz[(size_t)BATCH * TSEQ * 4 * HID];  // 256 MB scratch
__device__ float g_h1[(size_t)BATCH * TSEQ * HID];      //  64 MB scratch

__device__ __forceinline__ void fma2(ull& d, ull a, ull b) {
    asm("fma.rn.f32x2 %0, %1, %2, %0;" : "+l"(d) : "l"(a), "l"(b));
}
__device__ __forceinline__ ull pack2(float lo, float hi) {
    ull r; asm("mov.b64 %0, {%1, %2};" : "=l"(r) : "f"(lo), "f"(hi)); return r;
}
__device__ __forceinline__ float2 unpack2(ull v) {
    float2 r; asm("mov.b64 {%0, %1}, %2;" : "=f"(r.x), "=f"(r.y) : "l"(v)); return r;
}
__device__ __forceinline__ ull d2u(double d) { return (ull)__double_as_longlong(d); }

// ============================================================================
// GEMM: Y[M,512] = X[M,K] @ W[K,512] + bias.  BM=128, BN=128, K loaded whole.
// ============================================================================
template<int K>
__global__ __launch_bounds__(256, 1)
void gemm_xz(const float* __restrict__ X, const float* __restrict__ W,
             const float* __restrict__ bias, float* __restrict__ Y) {
    extern __shared__ float sm[];
    float* s_a = sm;                     // [128][K+1]
    float* s_b = sm + 128 * (K + 1);     // [K][128]
    const int tid = threadIdx.x;
    const int bm  = blockIdx.x * 128;
    const int bn  = blockIdx.y * 128;

    #pragma unroll 8
    for (int i = tid; i < 128 * K; i += 256) {
        int m = i / K, k = i - m * K;
        s_a[m * (K + 1) + k] = X[(size_t)(bm + m) * K + k];
    }
    #pragma unroll 4
    for (int i = tid * 4; i < K * 128; i += 1024) {
        int k = i >> 7, n = i & 127;
        *(float4*)(s_b + k * 128 + n) = *(const float4*)(W + (size_t)k * 512 + bn + n);
    }
    __syncthreads();

    const int tmi = tid & 15;
    const int tn  = (tid >> 4) << 3;
    ull acc[8][4] = {};
    const float* sbp = s_b + tn;

    #pragma unroll 4
    for (int k = 0; k < K; ++k) {
        float4 b0 = *(const float4*)(sbp + k * 128);
        float4 b1 = *(const float4*)(sbp + k * 128 + 4);
        ull bb0 = pack2(b0.x, b0.y), bb1 = pack2(b0.z, b0.w);
        ull bb2 = pack2(b1.x, b1.y), bb3 = pack2(b1.z, b1.w);
        #pragma unroll
        for (int r = 0; r < 8; ++r) {
            float a = s_a[(tmi + (r << 4)) * (K + 1) + k];
            ull aa = pack2(a, a);
            fma2(acc[r][0], aa, bb0);
            fma2(acc[r][1], aa, bb1);
            fma2(acc[r][2], aa, bb2);
            fma2(acc[r][3], aa, bb3);
        }
    }

    float4 bv0 = *(const float4*)(bias + bn + tn);
    float4 bv1 = *(const float4*)(bias + bn + tn + 4);
    #pragma unroll
    for (int r = 0; r < 8; ++r) {
        int row = bm + tmi + (r << 4);
        float2 c0 = unpack2(acc[r][0]);
        float2 c1 = unpack2(acc[r][1]);
        float2 c2 = unpack2(acc[r][2]);
        float2 c3 = unpack2(acc[r][3]);
        float4 o0 = make_float4(c0.x + bv0.x, c0.y + bv0.y, c1.x + bv0.z, c1.y + bv0.w);
        float4 o1 = make_float4(c2.x + bv1.x, c2.y + bv1.y, c3.x + bv1.z, c3.y + bv1.w);
        float* yp = Y + (size_t)row * 512 + bn + tn;
        *(float4*)yp       = o0;
        *(float4*)(yp + 4) = o1;
    }
}

// ============================================================================
// LSTM scan, 2 batch rows per CTA.
// ============================================================================
#define KREG 72
#define KSM  56

__global__ __launch_bounds__(512, 1)
void lstm_scan(const float* __restrict__ xz, const float* __restrict__ U,
               float* __restrict__ hout, int T) {
    extern __shared__ float sm[];
    float* s_u = sm;                       // [KSM/4][512][4]
    float* s_h = sm + (KSM / 4) * 2048;    // [2 rows][2 bufs][128]

    const int tid  = threadIdx.x;
    const int lane = tid & 31;
    const int gate = tid & 3;              // i, f, g, o
    const int j    = tid >> 2;             // 0..127
    const int ucol = (gate << 7) + j;
    const int b0   = blockIdx.x * 2;

    // ---- one-time U load ----------------------------------------------------
    ull ureg[KREG / 2];
    #pragma unroll
    for (int q = 0; q < KREG / 2; ++q) {
        float u0 = U[(size_t)(2 * q)     * 512 + ucol];
        float u1 = U[(size_t)(2 * q + 1) * 512 + ucol];
        ureg[q] = pack2(u0, u1);
    }
    #pragma unroll
    for (int kk = 0; kk < KSM; ++kk) {
        s_u[(kk >> 2) * 2048 + (tid << 2) + (kk & 3)] = U[(size_t)(KREG + kk) * 512 + ucol];
    }
    if (tid < HID) { s_h[tid] = 0.0f; s_h[256 + tid] = 0.0f; }  // buf0, both rows
    float c0 = 0.0f, c1 = 0.0f;
    __syncthreads();

    const float* xzp0 = xz + (size_t)b0 * T * 512 + ucol;
    const float* xzp1 = xzp0 + (size_t)T * 512;
    float* hp0 = hout + (size_t)b0 * T * HID + j;
    float* hp1 = hp0 + (size_t)T * HID;

    float xa0 = __ldcs(xzp0), xb0 = __ldcs(xzp0 + 512);
    float xa1 = __ldcs(xzp1), xb1 = __ldcs(xzp1 + 512);

    const int lb = lane & 28;              // 4-lane gate-group base

    for (int t = 0; t < T; ++t) {
        const int ib = t & 1;
        const int nb = ib ^ 1;
        const float* h0 = s_h + ib * 128;          // row0 current h
        const float* h1 = s_h + 256 + ib * 128;    // row1 current h

        // z_r = xz_r + dot(h_r, U[:,ucol]); 2 accumulator chains per row,
        // rows interleaved for ILP, U operands shared between rows.
        ull p0 = 0, q0 = 0, p1 = 0, q1 = 0;
        #pragma unroll
        for (int q = 0; q < KREG / 4; ++q) {
            double2 d0 = *(const double2*)(h0 + (q << 2));
            double2 d1 = *(const double2*)(h1 + (q << 2));
            fma2(p0, d2u(d0.x), ureg[2 * q]);
            fma2(p1, d2u(d1.x), ureg[2 * q]);
            fma2(q0, d2u(d0.y), ureg[2 * q + 1]);
            fma2(q1, d2u(d1.y), ureg[2 * q + 1]);
        }
        #pragma unroll
        for (int q = 0; q < KSM / 4; ++q) {
            double2 ud = *(const double2*)(s_u + q * 2048 + (tid << 2));
            double2 d0 = *(const double2*)(h0 + KREG + (q << 2));
            double2 d1 = *(const double2*)(h1 + KREG + (q << 2));
            fma2(p0, d2u(d0.x), d2u(ud.x));
            fma2(p1, d2u(d1.x), d2u(ud.x));
            fma2(q0, d2u(d0.y), d2u(ud.y));
            fma2(q1, d2u(d1.y), d2u(ud.y));
        }
        float2 e0 = unpack2(p0), f0 = unpack2(q0);
        float2 e1 = unpack2(p1), f1 = unpack2(q1);
        float z0 = xa0 + ((e0.x + e0.y) + (f0.x + f0.y));
        float z1 = xa1 + ((e1.x + e1.y) + (f1.x + f1.y));

        // rotate xz prefetch (depth 2)
        int tp = (t + 2 < T) ? t + 2 : t;
        xa0 = xb0; xb0 = __ldcs(xzp0 + (size_t)tp * 512);
        xa1 = xb1; xb1 = __ldcs(xzp1 + (size_t)tp * 512);

        // activations (sigmoid for i/f/o, selu for g), both rows
        float ex0  = __expf(gate == 2 ? z0 : -z0);
        float ex1  = __expf(gate == 2 ? z1 : -z1);
        float sg0  = __fdividef(1.0f, 1.0f + ex0);
        float sg1  = __fdividef(1.0f, 1.0f + ex1);
        float act0 = (gate == 2)
                   ? ((z0 > 0.0f) ? SELU_LAM * z0 : (SELU_LAM * SELU_ALF) * (ex0 - 1.0f))
                   : sg0;
        float act1 = (gate == 2)
                   ? ((z1 > 0.0f) ? SELU_LAM * z1 : (SELU_LAM * SELU_ALF) * (ex1 - 1.0f))
                   : sg1;

        // gather gates f, g, o into the gate==0 lane (3 shuffles per row)
        float af0 = __shfl_sync(0xffffffffu, act0, lb | 1);
        float af1 = __shfl_sync(0xffffffffu, act1, lb | 1);
        float ag0 = __shfl_sync(0xffffffffu, act0, lb | 2);
        float ag1 = __shfl_sync(0xffffffffu, act1, lb | 2);
        float ao0 = __shfl_sync(0xffffffffu, act0, lb | 3);
        float ao1 = __shfl_sync(0xffffffffu, act1, lb | 3);

        if (gate == 0) {
            c0 = af0 * c0 + act0 * ag0;
            c1 = af1 * c1 + act1 * ag1;
            float sc0 = (c0 > 0.0f) ? SELU_LAM * c0
                                    : (SELU_LAM * SELU_ALF) * (__expf(c0) - 1.0f);
            float sc1 = (c1 > 0.0f) ? SELU_LAM * c1
                                    : (SELU_LAM * SELU_ALF) * (__expf(c1) - 1.0f);
            float hh0 = ao0 * sc0;
            float hh1 = ao1 * sc1;
            s_h[nb * 128 + j]       = hh0;
            s_h[256 + nb * 128 + j] = hh1;
            hp0[(size_t)t * HID] = hh0;
            hp1[(size_t)t * HID] = hh1;
        }
        __syncthreads();
    }
}

// ============================================================================
// kernel_launch — inputs: x, W1, U1, b1, W2, U2, b2 (fp32); out: [B,T,H] fp32.
// ============================================================================
extern "C" void kernel_launch(void* const* d_in, const int* in_sizes, int n_in,
                              void* d_out, int out_size) {
    (void)in_sizes; (void)n_in; (void)out_size;
    const float* x  = (const float*)d_in[0];
    const float* W1 = (const float*)d_in[1];
    const float* U1 = (const float*)d_in[2];
    const float* b1 = (const float*)d_in[3];
    const float* W2 = (const float*)d_in[4];
    const float* U2 = (const float*)d_in[5];
    const float* b2 = (const float*)d_in[6];
    float* out = (float*)d_out;

    void *pxz = nullptr, *ph1 = nullptr;
    cudaGetSymbolAddress(&pxz, g_xz);
    cudaGetSymbolAddress(&ph1, g_h1);
    float* xz = (float*)pxz;
    float* h1 = (float*)ph1;

    const int smemA = (128 * (FIN + 1) + FIN * 128) * 4;    //  66048 B
    const int smemB = (128 * (HID + 1) + HID * 128) * 4;    // 131584 B
    const int smemS = ((KSM / 4) * 2048 + 512) * 4;         // 116736 B
    cudaFuncSetAttribute(gemm_xz<FIN>, cudaFuncAttributeMaxDynamicSharedMemorySize, smemA);
    cudaFuncSetAttribute(gemm_xz<HID>, cudaFuncAttributeMaxDynamicSharedMemorySize, smemB);
    cudaFuncSetAttribute(lstm_scan,    cudaFuncAttributeMaxDynamicSharedMemorySize, smemS);

    dim3 gg((BATCH * TSEQ) / 128, 4);

    gemm_xz<FIN><<<gg, 256, smemA>>>(x, W1, b1, xz);
    lstm_scan<<<BATCH / 2, 512, smemS>>>(xz, U1, h1, TSEQ);
    gemm_xz<HID><<<gg, 256, smemB>>>(h1, W2, b2, xz);
    lstm_scan<<<BATCH / 2, 512, smemS>>>(xz, U2, out, TSEQ);
}